// round 6
// baseline (speedup 1.0000x reference)
#include <cuda_runtime.h>
#include <cuda_fp16.h>
#include <cstdint>
#include <cstddef>

// ============================================================================
// B=16, W_DIM=512, C=1024, H=W=64  -> GEMM: M=65536, N=1024, K=1024 (fp16 in, f32 acc)
// NOTE: harness PTX target is compute_103 (no 'a') -> tcgen05/TMEM unavailable.
// Use mma.sync.m16n8k16 (HMMA) + cp.async pipeline instead.
// ============================================================================

__device__ float4  g_params[16 * 1024];                  // fx*2pi, fy*2pi, ph*2pi, amp
__device__ __half  g_feat[(size_t)65536 * 1024];         // fp16 features, K-major
__device__ __half  g_wt[(size_t)1024 * 1024];            // fp16 weight/32, K-major

__device__ __forceinline__ uint32_t smem_u32(const void* p) {
    uint32_t a;
    asm("{ .reg .u64 t; cvta.to.shared.u64 t, %1; cvt.u32.u64 %0, t; }" : "=r"(a) : "l"(p));
    return a;
}
__device__ __forceinline__ void cp_async16(uint32_t dst, const void* src) {
    asm volatile("cp.async.cg.shared.global [%0], [%1], 16;\n" :: "r"(dst), "l"(src));
}
__device__ __forceinline__ void cp_commit() { asm volatile("cp.async.commit_group;\n" ::: "memory"); }
template <int N> __device__ __forceinline__ void cp_wait() {
    asm volatile("cp.async.wait_group %0;\n" :: "n"(N) : "memory");
}

// ============================================================================
// Kernel 1: per-batch affine + per-channel params  (grid 16, 128 thr)
// ============================================================================
__global__ void k_setup(const float* __restrict__ w, const float* __restrict__ freqs,
                        const float* __restrict__ phases, const float* __restrict__ affine_w,
                        const float* __restrict__ affine_b) {
    __shared__ float t_sm[4];
    __shared__ float cs[4];
    int b = blockIdx.x;
    int tid = threadIdx.x, wid = tid >> 5, lane = tid & 31;

    float sum = 0.f;
    const float* wr = w + b * 512;
    const float* ar = affine_w + wid * 512;
    for (int j = lane; j < 512; j += 32) sum += wr[j] * ar[j];
    for (int o = 16; o; o >>= 1) sum += __shfl_xor_sync(0xffffffffu, sum, o);
    if (lane == 0) t_sm[wid] = sum * (1.0f / 22.627416997969522f) + affine_b[wid];
    __syncthreads();
    if (tid == 0) {
        float t0 = t_sm[0], t1 = t_sm[1], t2 = t_sm[2], t3 = t_sm[3];
        float inv = rsqrtf(t0 * t0 + t1 * t1);
        float c = t0 * inv, s = t1 * inv, tx = t2 * inv, ty = t3 * inv;
        cs[0] = c; cs[1] = s;
        cs[2] = -(c * tx - s * ty);   // trans_x
        cs[3] = -(s * tx + c * ty);   // trans_y
    }
    __syncthreads();
    float c = cs[0], s = cs[1], trx = cs[2], tryy = cs[3];
    const float TWO_PI = 6.283185307179586f;
    for (int ch = tid; ch < 1024; ch += 128) {
        float fx = freqs[ch * 2], fy = freqs[ch * 2 + 1];
        float ph = phases[ch] + fx * trx + fy * tryy;      // original freqs here
        float fbx = fx * c + fy * s;                        // f @ R
        float fby = -fx * s + fy * c;
        float r = sqrtf(fbx * fbx + fby * fby);
        float amp = 1.0f - (r - 2.0f) * (1.0f / 30.0f);
        amp = fminf(fmaxf(amp, 0.0f), 1.0f);
        g_params[b * 1024 + ch] = make_float4(fbx * TWO_PI, fby * TWO_PI, ph * TWO_PI, amp);
    }
}

// ============================================================================
// Kernel 2: weight -> fp16 * (1/sqrt(1024))
// ============================================================================
__global__ __launch_bounds__(256) void k_wt(const float* __restrict__ wt) {
    size_t i = (size_t)blockIdx.x * 256 + threadIdx.x;
    g_wt[i] = __float2half(wt[i] * 0.03125f);
}

// ============================================================================
// Kernel 3: fp16 feature map.  block = (b,h): m = b*4096 + h*64 + w
// ============================================================================
__global__ __launch_bounds__(256) void k_feat() {
    __shared__ float sfx[1024], sbase[1024], samp[1024];
    int bx = blockIdx.x;
    int b = bx >> 6, h = bx & 63;
    int tid = threadIdx.x;
    float v = (h + 0.5f) * (1.0f / 64.0f) - 0.5f;
    for (int ch = tid; ch < 1024; ch += 256) {
        float4 p = g_params[b * 1024 + ch];
        sfx[ch] = p.x;
        sbase[ch] = p.y * v + p.z;
        samp[ch] = p.w;
    }
    __syncthreads();
    int c0 = tid * 4;
    float fx0 = sfx[c0], fx1 = sfx[c0 + 1], fx2 = sfx[c0 + 2], fx3 = sfx[c0 + 3];
    float b0 = sbase[c0], b1 = sbase[c0 + 1], b2 = sbase[c0 + 2], b3 = sbase[c0 + 3];
    float a0 = samp[c0], a1 = samp[c0 + 1], a2 = samp[c0 + 2], a3 = samp[c0 + 3];
    __half* outp = g_feat + (size_t)bx * 64 * 1024 + c0;
#pragma unroll 4
    for (int wq = 0; wq < 64; wq++) {
        float u = (wq + 0.5f) * (1.0f / 64.0f) - 0.5f;
        float s0 = __sinf(fmaf(fx0, u, b0)) * a0;
        float s1 = __sinf(fmaf(fx1, u, b1)) * a1;
        float s2 = __sinf(fmaf(fx2, u, b2)) * a2;
        float s3 = __sinf(fmaf(fx3, u, b3)) * a3;
        union { __half2 h2[2]; uint2 u2; } cv;
        cv.h2[0] = __floats2half2_rn(s0, s1);
        cv.h2[1] = __floats2half2_rn(s2, s3);
        *reinterpret_cast<uint2*>(outp + (size_t)wq * 1024) = cv.u2;
    }
}

// ============================================================================
// Kernel 4: fp16 mma.sync GEMM.  C[m,n] = sum_k A[m,k]*B[n,k]
//   BM=128, BN=128, BK=64. 3-stage cp.async. 8 warps (2 M x 4 N), warp 64x32.
//   Smem rows padded to 72 halves (stride 36 words == 4 mod 32 -> conflict-free frags).
// ============================================================================
#define BM 128
#define BN 128
#define BK 64
#define AROW 72                               // halves per smem row (64 + 8 pad)
#define TILE_HALVES (BM * AROW)               // 9216 halves per operand tile
#define STAGE_HALVES (2 * TILE_HALVES)        // A + B
#define NST 3
#define GEMM_SMEM (NST * STAGE_HALVES * 2)    // bytes = 110592

__device__ __forceinline__ void load_stage(uint32_t sbase, int slot,
                                           const __half* Ag, const __half* Bg, int tid) {
    uint32_t st = sbase + slot * (STAGE_HALVES * 2);
#pragma unroll
    for (int t = 0; t < 4; t++) {
        int cid = tid + t * 256;
        int row = cid >> 3, j = cid & 7;
        cp_async16(st + row * 144 + j * 16, Ag + (size_t)row * 1024 + j * 8);
    }
    uint32_t stB = st + TILE_HALVES * 2;
#pragma unroll
    for (int t = 0; t < 4; t++) {
        int cid = tid + t * 256;
        int row = cid >> 3, j = cid & 7;
        cp_async16(stB + row * 144 + j * 16, Bg + (size_t)row * 1024 + j * 8);
    }
}

__global__ __launch_bounds__(256, 1) void k_gemm(float* __restrict__ out) {
    extern __shared__ __half smem_h[];
    uint32_t sb = smem_u32(smem_h);
    int tid = threadIdx.x, wid = tid >> 5, lane = tid & 31;
    int warp_m = wid >> 2;        // 0..1  (64 rows each)
    int warp_n = wid & 3;         // 0..3  (32 cols each)
    int g = lane >> 2;            // groupID 0..7
    int kq = lane & 3;            // thread-in-group

    int n0 = blockIdx.x * BN;
    int m0 = blockIdx.y * BM;

    const __half* Abase = g_feat + (size_t)m0 * 1024;
    const __half* Bbase = g_wt + (size_t)n0 * 1024;

    float acc[4][4][4];
#pragma unroll
    for (int mt = 0; mt < 4; mt++)
#pragma unroll
        for (int nt = 0; nt < 4; nt++)
#pragma unroll
            for (int r = 0; r < 4; r++) acc[mt][nt][r] = 0.f;

    // prologue: stages 0,1
    load_stage(sb, 0, Abase, Bbase, tid);
    cp_commit();
    load_stage(sb, 1, Abase + 64, Bbase + 64, tid);
    cp_commit();

    for (int i = 0; i < 16; i++) {
        if (i < 15) cp_wait<1>(); else cp_wait<0>();
        __syncthreads();
        if (i + 2 < 16) {
            load_stage(sb, (i + 2) % NST, Abase + (size_t)(i + 2) * 64,
                       Bbase + (size_t)(i + 2) * 64, tid);
            cp_commit();
        }
        const __half* As = smem_h + (i % NST) * STAGE_HALVES;
        const __half* Bs = As + TILE_HALVES;
        const __half* pa = As + (warp_m * 64 + g) * AROW + kq * 2;
        const __half* pb = Bs + (warp_n * 32 + g) * AROW + kq * 2;

#pragma unroll
        for (int ks = 0; ks < 4; ks++) {
            uint32_t afr[4][4], bfr[4][2];
#pragma unroll
            for (int mt = 0; mt < 4; mt++) {
                const __half* p = pa + mt * 16 * AROW + ks * 16;
                afr[mt][0] = *(const uint32_t*)(p);              // (g,    k0..1)
                afr[mt][1] = *(const uint32_t*)(p + 8 * AROW);   // (g+8,  k0..1)
                afr[mt][2] = *(const uint32_t*)(p + 8);          // (g,    k8..9)
                afr[mt][3] = *(const uint32_t*)(p + 8 * AROW + 8);
            }
#pragma unroll
            for (int nt = 0; nt < 4; nt++) {
                const __half* p = pb + nt * 8 * AROW + ks * 16;
                bfr[nt][0] = *(const uint32_t*)(p);              // (n=g, k0..1)
                bfr[nt][1] = *(const uint32_t*)(p + 8);          // (n=g, k8..9)
            }
#pragma unroll
            for (int mt = 0; mt < 4; mt++)
#pragma unroll
                for (int nt = 0; nt < 4; nt++)
                    asm volatile(
                        "mma.sync.aligned.m16n8k16.row.col.f32.f16.f16.f32 "
                        "{%0,%1,%2,%3}, {%4,%5,%6,%7}, {%8,%9}, {%0,%1,%2,%3};"
                        : "+f"(acc[mt][nt][0]), "+f"(acc[mt][nt][1]),
                          "+f"(acc[mt][nt][2]), "+f"(acc[mt][nt][3])
                        : "r"(afr[mt][0]), "r"(afr[mt][1]),
                          "r"(afr[mt][2]), "r"(afr[mt][3]),
                          "r"(bfr[nt][0]), "r"(bfr[nt][1]));
        }
    }

    // Epilogue. c0:(row g, col 2kq) c1:(g, 2kq+1) c2:(g+8, 2kq) c3:(g+8, 2kq+1)
    // out[b][n][hw]: b = m>>12 (const per CTA), hw = m & 4095. m contiguous across g -> 32B sectors.
    int b = m0 >> 12;
#pragma unroll
    for (int mt = 0; mt < 4; mt++) {
        int m_lo = m0 + warp_m * 64 + mt * 16 + g;
        int hw0 = m_lo & 4095;
        int hw1 = hw0 + 8;
#pragma unroll
        for (int nt = 0; nt < 4; nt++) {
            int n = n0 + warp_n * 32 + nt * 8 + kq * 2;
            float* o0 = out + ((size_t)(b * 1024 + n)) * 4096;
            float* o1 = o0 + 4096;
            o0[hw0] = acc[mt][nt][0];
            o1[hw0] = acc[mt][nt][1];
            o0[hw1] = acc[mt][nt][2];
            o1[hw1] = acc[mt][nt][3];
        }
    }
}

// ============================================================================
// launch
// ============================================================================
extern "C" void kernel_launch(void* const* d_in, const int* in_sizes, int n_in,
                              void* d_out, int out_size) {
    const float* w        = (const float*)d_in[0];
    const float* freqs    = (const float*)d_in[1];
    const float* phases   = (const float*)d_in[2];
    const float* weight   = (const float*)d_in[3];
    const float* affine_w = (const float*)d_in[4];
    const float* affine_b = (const float*)d_in[5];
    float* out = (float*)d_out;

    cudaFuncSetAttribute(k_gemm, cudaFuncAttributeMaxDynamicSharedMemorySize, GEMM_SMEM);

    k_setup<<<16, 128>>>(w, freqs, phases, affine_w, affine_b);
    k_wt<<<4096, 256>>>(weight);
    k_feat<<<1024, 256>>>();
    k_gemm<<<dim3(8, 512), 256, GEMM_SMEM>>>(out);
}

// round 7
// speedup vs baseline: 1.0636x; 1.0636x over previous
#include <cuda_runtime.h>
#include <cuda_fp16.h>
#include <cstdint>
#include <cstddef>

// ============================================================================
// B=16, W_DIM=512, C=1024, H=W=64  -> GEMM: M=65536, N=1024, K=1024 (fp16 in, f32 acc)
// compute_103 PTX target: no tcgen05 -> mma.sync.m16n8k16 HMMA + cp.async + ldmatrix.
// R7: 512 threads (16 warps, 4/SMSP), BM=128 BN=256, LDSM.x4 fragment loads.
// ============================================================================

__device__ float4  g_params[16 * 1024];                  // fx*2pi, fy*2pi, ph*2pi, amp
__device__ __half  g_feat[(size_t)65536 * 1024];         // fp16 features, K-major
__device__ __half  g_wt[(size_t)1024 * 1024];            // fp16 weight/32, K-major

__device__ __forceinline__ uint32_t smem_u32(const void* p) {
    uint32_t a;
    asm("{ .reg .u64 t; cvta.to.shared.u64 t, %1; cvt.u32.u64 %0, t; }" : "=r"(a) : "l"(p));
    return a;
}
__device__ __forceinline__ void cp_async16(uint32_t dst, const void* src) {
    asm volatile("cp.async.cg.shared.global [%0], [%1], 16;\n" :: "r"(dst), "l"(src));
}
__device__ __forceinline__ void cp_commit() { asm volatile("cp.async.commit_group;\n" ::: "memory"); }
template <int N> __device__ __forceinline__ void cp_wait() {
    asm volatile("cp.async.wait_group %0;\n" :: "n"(N) : "memory");
}
__device__ __forceinline__ void ldsm_x4(uint32_t& r0, uint32_t& r1, uint32_t& r2, uint32_t& r3,
                                        uint32_t addr) {
    asm volatile("ldmatrix.sync.aligned.m8n8.x4.shared.b16 {%0,%1,%2,%3}, [%4];"
                 : "=r"(r0), "=r"(r1), "=r"(r2), "=r"(r3) : "r"(addr));
}

// ============================================================================
// Kernel 1: per-batch affine + per-channel params  (grid 16, 128 thr)
// ============================================================================
__global__ void k_setup(const float* __restrict__ w, const float* __restrict__ freqs,
                        const float* __restrict__ phases, const float* __restrict__ affine_w,
                        const float* __restrict__ affine_b) {
    __shared__ float t_sm[4];
    __shared__ float cs[4];
    int b = blockIdx.x;
    int tid = threadIdx.x, wid = tid >> 5, lane = tid & 31;

    float sum = 0.f;
    const float* wr = w + b * 512;
    const float* ar = affine_w + wid * 512;
    for (int j = lane; j < 512; j += 32) sum += wr[j] * ar[j];
    for (int o = 16; o; o >>= 1) sum += __shfl_xor_sync(0xffffffffu, sum, o);
    if (lane == 0) t_sm[wid] = sum * (1.0f / 22.627416997969522f) + affine_b[wid];
    __syncthreads();
    if (tid == 0) {
        float t0 = t_sm[0], t1 = t_sm[1], t2 = t_sm[2], t3 = t_sm[3];
        float inv = rsqrtf(t0 * t0 + t1 * t1);
        float c = t0 * inv, s = t1 * inv, tx = t2 * inv, ty = t3 * inv;
        cs[0] = c; cs[1] = s;
        cs[2] = -(c * tx - s * ty);   // trans_x
        cs[3] = -(s * tx + c * ty);   // trans_y
    }
    __syncthreads();
    float c = cs[0], s = cs[1], trx = cs[2], tryy = cs[3];
    const float TWO_PI = 6.283185307179586f;
    for (int ch = tid; ch < 1024; ch += 128) {
        float fx = freqs[ch * 2], fy = freqs[ch * 2 + 1];
        float ph = phases[ch] + fx * trx + fy * tryy;      // original freqs here
        float fbx = fx * c + fy * s;                        // f @ R
        float fby = -fx * s + fy * c;
        float r = sqrtf(fbx * fbx + fby * fby);
        float amp = 1.0f - (r - 2.0f) * (1.0f / 30.0f);
        amp = fminf(fmaxf(amp, 0.0f), 1.0f);
        g_params[b * 1024 + ch] = make_float4(fbx * TWO_PI, fby * TWO_PI, ph * TWO_PI, amp);
    }
}

// ============================================================================
// Kernel 2: weight -> fp16 * (1/sqrt(1024))
// ============================================================================
__global__ __launch_bounds__(256) void k_wt(const float* __restrict__ wt) {
    size_t i = (size_t)blockIdx.x * 256 + threadIdx.x;
    g_wt[i] = __float2half(wt[i] * 0.03125f);
}

// ============================================================================
// Kernel 3: fp16 feature map.  block = (b,h): m = b*4096 + h*64 + w
// ============================================================================
__global__ __launch_bounds__(256) void k_feat() {
    __shared__ float sfx[1024], sbase[1024], samp[1024];
    int bx = blockIdx.x;
    int b = bx >> 6, h = bx & 63;
    int tid = threadIdx.x;
    float v = (h + 0.5f) * (1.0f / 64.0f) - 0.5f;
    for (int ch = tid; ch < 1024; ch += 256) {
        float4 p = g_params[b * 1024 + ch];
        sfx[ch] = p.x;
        sbase[ch] = p.y * v + p.z;
        samp[ch] = p.w;
    }
    __syncthreads();
    int c0 = tid * 4;
    float fx0 = sfx[c0], fx1 = sfx[c0 + 1], fx2 = sfx[c0 + 2], fx3 = sfx[c0 + 3];
    float b0 = sbase[c0], b1 = sbase[c0 + 1], b2 = sbase[c0 + 2], b3 = sbase[c0 + 3];
    float a0 = samp[c0], a1 = samp[c0 + 1], a2 = samp[c0 + 2], a3 = samp[c0 + 3];
    __half* outp = g_feat + (size_t)bx * 64 * 1024 + c0;
#pragma unroll 4
    for (int wq = 0; wq < 64; wq++) {
        float u = (wq + 0.5f) * (1.0f / 64.0f) - 0.5f;
        float s0 = __sinf(fmaf(fx0, u, b0)) * a0;
        float s1 = __sinf(fmaf(fx1, u, b1)) * a1;
        float s2 = __sinf(fmaf(fx2, u, b2)) * a2;
        float s3 = __sinf(fmaf(fx3, u, b3)) * a3;
        union { __half2 h2[2]; uint2 u2; } cv;
        cv.h2[0] = __floats2half2_rn(s0, s1);
        cv.h2[1] = __floats2half2_rn(s2, s3);
        *reinterpret_cast<uint2*>(outp + (size_t)wq * 1024) = cv.u2;
    }
}

// ============================================================================
// Kernel 4: fp16 mma.sync GEMM.  C[m,n] = sum_k A[m,k]*B[n,k]
//   BM=128, BN=256, BK=64. 3-stage cp.async. 16 warps (2 M x 8 N), warp 64x32.
//   Rows padded to 72 halves (144 B stride == 4 banks mod 32 -> LDSM conflict-free).
// ============================================================================
#define BM 128
#define BN 256
#define AROW 72
#define ROWB (AROW * 2)                       // 144 bytes per smem row
#define A_TILE_H (BM * AROW)                  // 9216 halves
#define B_TILE_H (BN * AROW)                  // 18432 halves
#define STAGE_H (A_TILE_H + B_TILE_H)         // 27648 halves (55296 B)
#define NST 3
#define GEMM_SMEM (NST * STAGE_H * 2)         // 165888 bytes

__device__ __forceinline__ void load_stage(uint32_t st, const __half* Ag,
                                           const __half* Bg, int tid) {
#pragma unroll
    for (int t = 0; t < 2; t++) {             // A: 128 rows x 8 chunks = 1024
        int cid = tid + t * 512;
        int row = cid >> 3, j = cid & 7;
        cp_async16(st + row * ROWB + j * 16, Ag + (size_t)row * 1024 + j * 8);
    }
    uint32_t stB = st + A_TILE_H * 2;
#pragma unroll
    for (int t = 0; t < 4; t++) {             // B: 256 rows x 8 chunks = 2048
        int cid = tid + t * 512;
        int row = cid >> 3, j = cid & 7;
        cp_async16(stB + row * ROWB + j * 16, Bg + (size_t)row * 1024 + j * 8);
    }
}

__global__ __launch_bounds__(512, 1) void k_gemm(float* __restrict__ out) {
    extern __shared__ __half smem_h[];
    uint32_t sb = smem_u32(smem_h);
    int tid = threadIdx.x, wid = tid >> 5, lane = tid & 31;
    int warp_m = wid >> 3;        // 0..1  (64 rows each)
    int warp_n = wid & 7;         // 0..7  (32 cols each)
    int g = lane >> 2;            // groupID 0..7
    int kq = lane & 3;            // thread-in-group

    int n0 = blockIdx.x * BN;
    int m0 = blockIdx.y * BM;

    const __half* Abase = g_feat + (size_t)m0 * 1024;
    const __half* Bbase = g_wt + (size_t)n0 * 1024;

    // ldmatrix lane address components (within a stage's A / B tile)
    const uint32_t a_lane_off = (uint32_t)(warp_m * 64 + (lane & 15)) * ROWB + (lane >> 4) * 16;
    const uint32_t b_lane_off = (uint32_t)(warp_n * 32 + (lane & 15)) * ROWB + (lane >> 4) * 16;

    float acc[4][4][4];
#pragma unroll
    for (int mt = 0; mt < 4; mt++)
#pragma unroll
        for (int nt = 0; nt < 4; nt++)
#pragma unroll
            for (int r = 0; r < 4; r++) acc[mt][nt][r] = 0.f;

    // prologue: stages 0,1
    load_stage(sb, Abase, Bbase, tid);
    cp_commit();
    load_stage(sb + STAGE_H * 2, Abase + 64, Bbase + 64, tid);
    cp_commit();

    for (int i = 0; i < 16; i++) {
        if (i < 15) cp_wait<1>(); else cp_wait<0>();
        __syncthreads();
        if (i + 2 < 16) {
            load_stage(sb + ((i + 2) % NST) * (STAGE_H * 2),
                       Abase + (size_t)(i + 2) * 64, Bbase + (size_t)(i + 2) * 64, tid);
            cp_commit();
        }
        uint32_t As = sb + (i % NST) * (STAGE_H * 2);
        uint32_t Bs = As + A_TILE_H * 2;
        uint32_t a_base = As + a_lane_off;
        uint32_t b_base = Bs + b_lane_off;

#pragma unroll
        for (int ks = 0; ks < 4; ks++) {
            uint32_t afr[4][4], bq[2][4];
#pragma unroll
            for (int mt = 0; mt < 4; mt++)
                ldsm_x4(afr[mt][0], afr[mt][1], afr[mt][2], afr[mt][3],
                        a_base + mt * (16 * ROWB) + ks * 32);
#pragma unroll
            for (int ntp = 0; ntp < 2; ntp++)
                ldsm_x4(bq[ntp][0], bq[ntp][1], bq[ntp][2], bq[ntp][3],
                        b_base + ntp * (16 * ROWB) + ks * 32);
#pragma unroll
            for (int mt = 0; mt < 4; mt++)
#pragma unroll
                for (int nt = 0; nt < 4; nt++)
                    asm volatile(
                        "mma.sync.aligned.m16n8k16.row.col.f32.f16.f16.f32 "
                        "{%0,%1,%2,%3}, {%4,%5,%6,%7}, {%8,%9}, {%0,%1,%2,%3};"
                        : "+f"(acc[mt][nt][0]), "+f"(acc[mt][nt][1]),
                          "+f"(acc[mt][nt][2]), "+f"(acc[mt][nt][3])
                        : "r"(afr[mt][0]), "r"(afr[mt][1]),
                          "r"(afr[mt][2]), "r"(afr[mt][3]),
                          "r"(bq[nt >> 1][nt & 1]), "r"(bq[nt >> 1][(nt & 1) + 2]));
        }
    }

    // Epilogue. c0:(row g, col 2kq) c1:(g, 2kq+1) c2:(g+8, 2kq) c3:(g+8, 2kq+1)
    // out[b][n][hw]: b = m0>>12 (const per CTA), hw = m & 4095.
    int b = m0 >> 12;
#pragma unroll
    for (int mt = 0; mt < 4; mt++) {
        int m_lo = m0 + warp_m * 64 + mt * 16 + g;
        int hw0 = m_lo & 4095;
        int hw1 = hw0 + 8;
#pragma unroll
        for (int nt = 0; nt < 4; nt++) {
            int n = n0 + warp_n * 32 + nt * 8 + kq * 2;
            float* o0 = out + ((size_t)(b * 1024 + n)) * 4096;
            float* o1 = o0 + 4096;
            o0[hw0] = acc[mt][nt][0];
            o1[hw0] = acc[mt][nt][1];
            o0[hw1] = acc[mt][nt][2];
            o1[hw1] = acc[mt][nt][3];
        }
    }
}

// ============================================================================
// launch
// ============================================================================
extern "C" void kernel_launch(void* const* d_in, const int* in_sizes, int n_in,
                              void* d_out, int out_size) {
    const float* w        = (const float*)d_in[0];
    const float* freqs    = (const float*)d_in[1];
    const float* phases   = (const float*)d_in[2];
    const float* weight   = (const float*)d_in[3];
    const float* affine_w = (const float*)d_in[4];
    const float* affine_b = (const float*)d_in[5];
    float* out = (float*)d_out;

    cudaFuncSetAttribute(k_gemm, cudaFuncAttributeMaxDynamicSharedMemorySize, GEMM_SMEM);

    k_setup<<<16, 128>>>(w, freqs, phases, affine_w, affine_b);
    k_wt<<<4096, 256>>>(weight);
    k_feat<<<1024, 256>>>();
    k_gemm<<<dim3(4, 512), 512, GEMM_SMEM>>>(out);
}